// round 4
// baseline (speedup 1.0000x reference)
#include <cuda_runtime.h>
#include <math.h>

// Problem constants (fixed by the reference)
constexpr int HID   = 896;    // hidden
constexpr int INTR  = 2560;   // intermediate
constexpr int NEXP  = 16;     // experts
constexpr int TOPK  = 4;
constexpr int MAXT  = 2048;   // tokens (2*1024)
constexpr int ROWS_ROUTED = MAXT * TOPK;           // 8192 (exact)
constexpr int ROWS_TOTAL  = ROWS_ROUTED + MAXT;    // + shared expert rows

// ---------------- scratch (static __device__ -> allowed) ----------------
__device__ int   g_count[NEXP];
__device__ int   g_off[NEXP];          // exclusive prefix of counts
__device__ float g_probsum[NEXP];
__device__ int   g_tok[NEXP * MAXT];
__device__ float g_wt [NEXP * MAXT];
// compacted h activations: routed rows [0, 8192) grouped by expert, shared rows [8192, 10240)
__device__ float g_h[(size_t)ROWS_TOTAL * INTR];   // ~100 MB

// ---------------- kernel 1: zero outputs + counters ----------------
__global__ void zero_kernel(float* __restrict__ out, int n) {
    int i = blockIdx.x * blockDim.x + threadIdx.x;
    if (i < n) out[i] = 0.0f;
    if (blockIdx.x == 0 && threadIdx.x < NEXP) {
        g_count[threadIdx.x]   = 0;
        g_probsum[threadIdx.x] = 0.0f;
    }
}

// ---------------- kernel 2: router (1 warp per token) ----------------
__global__ void router_kernel(const float* __restrict__ x,
                              const float* __restrict__ rw, int T) {
    int warp = (blockIdx.x * blockDim.x + threadIdx.x) >> 5;
    int lane = threadIdx.x & 31;
    if (warp >= T) return;
    const float* xr = x + (size_t)warp * HID;

    // lanes 0..15 each own one expert's logit
    float logit = -1e30f;
    if (lane < NEXP) {
        float s = 0.0f;
        for (int d = 0; d < HID; d++) s += xr[d] * rw[d * NEXP + lane];
        logit = s;
    }
    // softmax over lanes 0..15 (xor-group {8,4,2,1} is closed within [0,16))
    float m = logit;
    #pragma unroll
    for (int o = 8; o >= 1; o >>= 1) m = fmaxf(m, __shfl_xor_sync(0xffffffffu, m, o));
    float p = (lane < NEXP) ? __expf(logit - m) : 0.0f;
    float sum = p;
    #pragma unroll
    for (int o = 8; o >= 1; o >>= 1) sum += __shfl_xor_sync(0xffffffffu, sum, o);
    p = p / sum;

    if (lane < NEXP) atomicAdd(&g_probsum[lane], p);

    // gather all 16 probs to every lane, lane 0 does top-4
    float pv[NEXP];
    #pragma unroll
    for (int e = 0; e < NEXP; e++) pv[e] = __shfl_sync(0xffffffffu, p, e);

    if (lane == 0) {
        bool used[NEXP];
        #pragma unroll
        for (int e = 0; e < NEXP; e++) used[e] = false;
        int   idx[TOPK];
        float val[TOPK];
        float s4 = 0.0f;
        #pragma unroll
        for (int k = 0; k < TOPK; k++) {
            int bi = -1; float bv = -1.0f;
            #pragma unroll
            for (int e = 0; e < NEXP; e++)
                if (!used[e] && pv[e] > bv) { bv = pv[e]; bi = e; }
            used[bi] = true; idx[k] = bi; val[k] = bv; s4 += bv;
        }
        float inv = 1.0f / (s4 + 1e-8f);
        #pragma unroll
        for (int k = 0; k < TOPK; k++) {
            int e = idx[k];
            int pos = atomicAdd(&g_count[e], 1);
            g_tok[e * MAXT + pos] = warp;
            g_wt [e * MAXT + pos] = val[k] * inv;
        }
    }
}

// ---------------- kernel 3: prefix offsets + balance loss ----------------
__global__ void finalize_kernel(float* __restrict__ out, int T, int ofs, int has_loss) {
    if (threadIdx.x == 0) {
        int s = 0;
        float loss = 0.0f;
        for (int e = 0; e < NEXP; e++) {
            g_off[e] = s;
            s += g_count[e];
            loss += ((float)g_count[e] / (float)T) * (g_probsum[e] / (float)T);
        }
        if (has_loss) out[ofs] = loss * (float)NEXP;
    }
}

// ---------------- kernel 4: GEMM1  h = silu(x*Wg) * (x*Wu) ----------------
// grid: (INTR/64, ceil(T/64), 17), block 256 (16x16), tile 64x64, BK=16
__global__ void gemm1_kernel(const float* __restrict__ x,
                             const float* __restrict__ Wg, const float* __restrict__ Wu,
                             const float* __restrict__ Sg, const float* __restrict__ Su,
                             int T) {
    int slot  = blockIdx.z;
    int rows  = (slot < NEXP) ? g_count[slot] : T;
    int mbase = blockIdx.y * 64;
    if (mbase >= rows) return;
    int n0 = blockIdx.x * 64;
    int rowbase = (slot < NEXP) ? g_off[slot] : ROWS_ROUTED;  // compacted h row base

    const float* Bg = (slot < NEXP) ? Wg + (size_t)slot * HID * INTR : Sg;
    const float* Bu = (slot < NEXP) ? Wu + (size_t)slot * HID * INTR : Su;

    __shared__ float Xs [16][64];
    __shared__ float Bgs[16][64];
    __shared__ float Bus[16][64];

    int tid = threadIdx.x;
    int tx = tid & 15, ty = tid >> 4;

    // A loader mapping: 4 threads per row, float4 each
    int lm = tid >> 2, lq = tid & 3;
    bool avalid = (mbase + lm) < rows;
    size_t xoff = 0;
    if (avalid) {
        int tok = (slot < NEXP) ? g_tok[slot * MAXT + mbase + lm] : (mbase + lm);
        xoff = (size_t)tok * HID;
    }
    // B loader mapping: 16 threads per row, float4 each
    int bk = tid >> 4, bn = tid & 15;

    float accg[4][4] = {}, accu[4][4] = {};

    for (int k0 = 0; k0 < HID; k0 += 16) {
        float4 av = make_float4(0.f, 0.f, 0.f, 0.f);
        if (avalid) av = *(const float4*)(x + xoff + k0 + lq * 4);
        Xs[lq * 4 + 0][lm] = av.x;
        Xs[lq * 4 + 1][lm] = av.y;
        Xs[lq * 4 + 2][lm] = av.z;
        Xs[lq * 4 + 3][lm] = av.w;
        *(float4*)&Bgs[bk][bn * 4] = *(const float4*)(Bg + (size_t)(k0 + bk) * INTR + n0 + bn * 4);
        *(float4*)&Bus[bk][bn * 4] = *(const float4*)(Bu + (size_t)(k0 + bk) * INTR + n0 + bn * 4);
        __syncthreads();
        #pragma unroll
        for (int kk = 0; kk < 16; kk++) {
            float4 a  = *(float4*)&Xs [kk][ty * 4];
            float4 b1 = *(float4*)&Bgs[kk][tx * 4];
            float4 b2 = *(float4*)&Bus[kk][tx * 4];
            float ar[4]  = {a.x,  a.y,  a.z,  a.w};
            float bgr[4] = {b1.x, b1.y, b1.z, b1.w};
            float bur[4] = {b2.x, b2.y, b2.z, b2.w};
            #pragma unroll
            for (int i = 0; i < 4; i++)
                #pragma unroll
                for (int j = 0; j < 4; j++) {
                    accg[i][j] += ar[i] * bgr[j];
                    accu[i][j] += ar[i] * bur[j];
                }
        }
        __syncthreads();
    }

    size_t hbase = (size_t)(rowbase + mbase) * INTR;
    #pragma unroll
    for (int i = 0; i < 4; i++) {
        int m = ty * 4 + i;
        if (mbase + m < rows) {
            float r[4];
            #pragma unroll
            for (int j = 0; j < 4; j++) {
                float g = accg[i][j];
                float s = g / (1.0f + __expf(-g));   // silu
                r[j] = s * accu[i][j];
            }
            float4 hv = make_float4(r[0], r[1], r[2], r[3]);
            *(float4*)(g_h + hbase + (size_t)m * INTR + n0 + tx * 4) = hv;
        }
    }
}

// ---------------- kernel 5: GEMM2  out += (h * Wd) * route_weight ----------------
// grid: (HID/64, ceil(T/64), 17), block 256, tile 64x64, BK=16
__global__ void gemm2_kernel(const float* __restrict__ Wd, const float* __restrict__ Sd,
                             float* __restrict__ out, int T) {
    int slot  = blockIdx.z;
    int rows  = (slot < NEXP) ? g_count[slot] : T;
    int mbase = blockIdx.y * 64;
    if (mbase >= rows) return;
    int n0 = blockIdx.x * 64;
    int rowbase = (slot < NEXP) ? g_off[slot] : ROWS_ROUTED;

    const float* Bw = (slot < NEXP) ? Wd + (size_t)slot * INTR * HID : Sd;

    __shared__ float As[16][64];
    __shared__ float Bs[16][64];

    int tid = threadIdx.x;
    int tx = tid & 15, ty = tid >> 4;
    int lm = tid >> 2, lq = tid & 3;
    int bk = tid >> 4, bn = tid & 15;

    bool avalid = (mbase + lm) < rows;
    size_t habase = (size_t)(rowbase + mbase) * INTR;

    float acc[4][4] = {};

    for (int k0 = 0; k0 < INTR; k0 += 16) {
        float4 av = make_float4(0.f, 0.f, 0.f, 0.f);
        if (avalid) av = *(const float4*)(g_h + habase + (size_t)lm * INTR + k0 + lq * 4);
        As[lq * 4 + 0][lm] = av.x;
        As[lq * 4 + 1][lm] = av.y;
        As[lq * 4 + 2][lm] = av.z;
        As[lq * 4 + 3][lm] = av.w;
        *(float4*)&Bs[bk][bn * 4] = *(const float4*)(Bw + (size_t)(k0 + bk) * HID + n0 + bn * 4);
        __syncthreads();
        #pragma unroll
        for (int kk = 0; kk < 16; kk++) {
            float4 a = *(float4*)&As[kk][ty * 4];
            float4 b = *(float4*)&Bs[kk][tx * 4];
            float ar[4] = {a.x, a.y, a.z, a.w};
            float br[4] = {b.x, b.y, b.z, b.w};
            #pragma unroll
            for (int i = 0; i < 4; i++)
                #pragma unroll
                for (int j = 0; j < 4; j++)
                    acc[i][j] += ar[i] * br[j];
        }
        __syncthreads();
    }

    #pragma unroll
    for (int i = 0; i < 4; i++) {
        int m = ty * 4 + i;
        int trow = mbase + m;
        if (trow < rows) {
            int   tok = (slot < NEXP) ? g_tok[slot * MAXT + trow] : trow;
            float w   = (slot < NEXP) ? g_wt [slot * MAXT + trow] : 1.0f;
            #pragma unroll
            for (int j = 0; j < 4; j++)
                atomicAdd(&out[(size_t)tok * HID + n0 + tx * 4 + j], acc[i][j] * w);
        }
    }
}

// ---------------- launcher ----------------
extern "C" void kernel_launch(void* const* d_in, const int* in_sizes, int n_in,
                              void* d_out, int out_size) {
    const float* x  = (const float*)d_in[0];
    const float* rw = (const float*)d_in[1];
    const float* Wg = (const float*)d_in[2];
    const float* Wu = (const float*)d_in[3];
    const float* Wd = (const float*)d_in[4];
    const float* Sg = (const float*)d_in[5];
    const float* Su = (const float*)d_in[6];
    const float* Sd = (const float*)d_in[7];
    float* out = (float*)d_out;

    int T = in_sizes[0] / HID;          // 2048
    int ntok = T * HID;

    zero_kernel<<<(ntok + 255) / 256, 256>>>(out, ntok);
    router_kernel<<<(T + 7) / 8, 256>>>(x, rw, T);
    finalize_kernel<<<1, 32>>>(out, T, ntok, (out_size > ntok) ? 1 : 0);

    dim3 g1(INTR / 64, (T + 63) / 64, NEXP + 1);
    gemm1_kernel<<<g1, 256>>>(x, Wg, Wu, Sg, Su, T);

    dim3 g2(HID / 64, (T + 63) / 64, NEXP + 1);
    gemm2_kernel<<<g2, 256>>>(Wd, Sd, out, T);
}